// round 2
// baseline (speedup 1.0000x reference)
#include <cuda_runtime.h>
#include <math.h>

// Problem sizes (fixed by the reference)
constexpr int NN = 2048;
constexpr int MM = 2048;
constexpr int DD = 16;

// ----- scratch (no allocations allowed -> __device__ globals) -----
__device__ float g_Xl [NN * DD];   // X / ls
__device__ float g_V  [NN * DD];   // 2*var*Xl*(L - l2)
__device__ float g_X2l[MM * DD];   // X2 / ls
__device__ float g_P  [NN];        // var*(s1 + (D-1-Xs)*L)
__device__ float g_hXs[NN];        // -0.5*Xs
__device__ float g_Q  [MM];        // var*(s2 - X2s*L)
__device__ float g_hX2s[MM];       // -0.5*X2s

// ---------------------------------------------------------------------------
// Prep: one thread per row (N + M rows). Cost is negligible.
// ---------------------------------------------------------------------------
__global__ void prep_kernel(const float* __restrict__ X,
                            const float* __restrict__ X2,
                            const float* __restrict__ uls,
                            const float* __restrict__ uv)
{
    int i = blockIdx.x * blockDim.x + threadIdx.x;
    if (i >= NN + MM) return;

    float inv_ls[DD], l2[DD];
    float L = 0.f;
#pragma unroll
    for (int d = 0; d < DD; ++d) {
        float u = uls[d];
        float s = (u > 20.f) ? u : log1pf(expf(u));   // softplus
        inv_ls[d] = 1.f / s;
        l2[d]     = inv_ls[d] * inv_ls[d];
        L += l2[d];
    }
    float u0  = uv[0];
    float var = (u0 > 20.f) ? u0 : log1pf(expf(u0));

    if (i < NN) {
        const float* xr = X + (size_t)i * DD;
        float xl[DD];
        float xs = 0.f, s1 = 0.f;
#pragma unroll
        for (int d = 0; d < DD; ++d) {
            float v = xr[d] * inv_ls[d];
            xl[d] = v;
            xs += v * v;
            s1 += v * v * l2[d];
        }
#pragma unroll
        for (int d = 0; d < DD; ++d) {
            g_Xl[i * DD + d] = xl[d];
            g_V [i * DD + d] = 2.f * var * xl[d] * (L - l2[d]);
        }
        g_P  [i] = var * (s1 + ((float)DD - 1.f - xs) * L);
        g_hXs[i] = -0.5f * xs;
    } else {
        int m = i - NN;
        const float* xr = X2 + (size_t)m * DD;
        float x2s = 0.f, s2 = 0.f;
#pragma unroll
        for (int d = 0; d < DD; ++d) {
            float v = xr[d] * inv_ls[d];
            g_X2l[m * DD + d] = v;
            x2s += v * v;
            s2  += v * v * l2[d];
        }
        g_Q   [m] = var * (s2 - x2s * L);
        g_hX2s[m] = -0.5f * x2s;
    }
}

// ---------------------------------------------------------------------------
// Main: out[n,m] = __expf(hXs[n] + hX2s[m] + Xl_n.X2l_m) * (P[n]+Q[m]+V_n.X2l_m)
// Block: 256 threads, 2 m-columns/thread (512 cols), 32 n-rows via smem.
// Grid: (2048/512, 2048/32) = (4, 64) = 256 blocks.
// ---------------------------------------------------------------------------
constexpr int TILE_N = 32;
constexpr int BT     = 256;

__global__ __launch_bounds__(BT, 2)
void main_kernel(float* __restrict__ out)
{
    __shared__ float4 sXl[TILE_N * (DD / 4)];
    __shared__ float4 sV [TILE_N * (DD / 4)];
    __shared__ float  sP [TILE_N];
    __shared__ float  sH [TILE_N];

    const int t  = threadIdx.x;
    const int nb = blockIdx.y * TILE_N;
    const int m0 = blockIdx.x * (2 * BT) + t;
    const int m1 = m0 + BT;

    // cooperative tile load (rows are contiguous in g_Xl/g_V)
    const float4* gXl4 = reinterpret_cast<const float4*>(g_Xl);
    const float4* gV4  = reinterpret_cast<const float4*>(g_V);
    for (int i = t; i < TILE_N * (DD / 4); i += BT) {
        sXl[i] = gXl4[nb * (DD / 4) + i];
        sV [i] = gV4 [nb * (DD / 4) + i];
    }
    if (t < TILE_N) { sP[t] = g_P[nb + t]; sH[t] = g_hXs[nb + t]; }

    // per-thread column data in registers
    float a[DD], b[DD];
    {
        const float4* ra = reinterpret_cast<const float4*>(g_X2l + (size_t)m0 * DD);
        const float4* rb = reinterpret_cast<const float4*>(g_X2l + (size_t)m1 * DD);
#pragma unroll
        for (int q = 0; q < DD / 4; ++q) {
            float4 va = ra[q];
            float4 vb = rb[q];
            a[4*q+0] = va.x; a[4*q+1] = va.y; a[4*q+2] = va.z; a[4*q+3] = va.w;
            b[4*q+0] = vb.x; b[4*q+1] = vb.y; b[4*q+2] = vb.z; b[4*q+3] = vb.w;
        }
    }
    const float qa = g_Q[m0], ha = g_hX2s[m0];
    const float qb = g_Q[m1], hb = g_hX2s[m1];

    __syncthreads();

#pragma unroll 2
    for (int n = 0; n < TILE_N; ++n) {
        float d0a = 0.f, dva = 0.f, d0b = 0.f, dvb = 0.f;
#pragma unroll
        for (int q = 0; q < DD / 4; ++q) {
            float4 x4 = sXl[n * (DD / 4) + q];   // broadcast LDS.128
            float4 v4 = sV [n * (DD / 4) + q];
            d0a += x4.x * a[4*q+0];  dva += v4.x * a[4*q+0];
            d0a += x4.y * a[4*q+1];  dva += v4.y * a[4*q+1];
            d0a += x4.z * a[4*q+2];  dva += v4.z * a[4*q+2];
            d0a += x4.w * a[4*q+3];  dva += v4.w * a[4*q+3];
            d0b += x4.x * b[4*q+0];  dvb += v4.x * b[4*q+0];
            d0b += x4.y * b[4*q+1];  dvb += v4.y * b[4*q+1];
            d0b += x4.z * b[4*q+2];  dvb += v4.z * b[4*q+2];
            d0b += x4.w * b[4*q+3];  dvb += v4.w * b[4*q+3];
        }
        const float pn = sP[n], hn = sH[n];
        float* orow = out + (size_t)(nb + n) * MM;
        orow[m0] = __expf(hn + ha + d0a) * (pn + qa + dva);
        orow[m1] = __expf(hn + hb + d0b) * (pn + qb + dvb);
    }
}

// ---------------------------------------------------------------------------
extern "C" void kernel_launch(void* const* d_in, const int* in_sizes, int n_in,
                              void* d_out, int out_size)
{
    const float* X   = (const float*)d_in[0];   // (2048,16)
    const float* X2  = (const float*)d_in[1];   // (2048,16)
    const float* uls = (const float*)d_in[2];   // (16,)
    const float* uv  = (const float*)d_in[3];   // (1,)
    float* out = (float*)d_out;                 // (2048,2048)

    prep_kernel<<<(NN + MM + 255) / 256, 256>>>(X, X2, uls, uv);

    dim3 grid(MM / (2 * BT), NN / TILE_N);      // (4, 64)
    main_kernel<<<grid, BT>>>(out);
}

// round 6
// speedup vs baseline: 1.2634x; 1.2634x over previous
#include <cuda_runtime.h>
#include <math.h>

constexpr int NN = 2048;
constexpr int MM = 2048;
constexpr int DD = 16;

constexpr int BT     = 128;        // threads per block
constexpr int TILE_N = 16;         // rows per block
constexpr int TILE_M = 2 * BT;     // 256 cols per block (2 adjacent cols/thread)

// ---------------------------------------------------------------------------
// Single fused kernel.
// out[n,m] = exp(hXs[n]+hX2s[m]+Xl_n.X2l_m) * (P[n]+Q[m]+c1*(Xl_n.X2l_m)-c2*(Xl_n.(l2∘X2l_m)))
//   c1 = 2*var*L,  c2 = 2*var,  L = sum(l2)
// ---------------------------------------------------------------------------
__global__ __launch_bounds__(BT)
void fused_kernel(const float* __restrict__ X,
                  const float* __restrict__ X2,
                  const float* __restrict__ uls,
                  const float* __restrict__ uv,
                  float* __restrict__ out)
{
    __shared__ float4 sXl[TILE_N * (DD / 4)];   // row tile, lengthscaled
    __shared__ float  sP [TILE_N];
    __shared__ float  sH [TILE_N];
    __shared__ float  sInv[DD];
    __shared__ float  sL2 [DD];
    __shared__ float  sVar;

    const int t  = threadIdx.x;
    const int nb = blockIdx.y * TILE_N;
    const int m0 = blockIdx.x * TILE_M + 2 * t;   // thread owns cols m0, m0+1

    // ---- phase 1: softplus of hyperparams (17 scalars) ----
    if (t < DD) {
        float u = uls[t];
        float s = (u > 20.f) ? u : log1pf(expf(u));
        float inv = 1.f / s;
        sInv[t] = inv;
        sL2[t]  = inv * inv;
    }
    if (t == DD) {
        float u = uv[0];
        sVar = (u > 20.f) ? u : log1pf(expf(u));
    }
    __syncthreads();

    float inv_ls[DD], l2[DD];
    float L = 0.f;
#pragma unroll
    for (int d = 0; d < DD; ++d) { inv_ls[d] = sInv[d]; l2[d] = sL2[d]; L += l2[d]; }
    const float var = sVar;
    const float c1  = 2.f * var * L;
    const float c2  = 2.f * var;

    // ---- phase 2a: row-tile prep (threads 0..TILE_N-1, one row each) ----
    if (t < TILE_N) {
        const float* xr = X + (size_t)(nb + t) * DD;
        float xl[DD];
        float xs = 0.f, s1 = 0.f;
#pragma unroll
        for (int d = 0; d < DD; ++d) {
            float v = xr[d] * inv_ls[d];
            xl[d] = v;
            xs += v * v;
            s1 += v * v * l2[d];
        }
#pragma unroll
        for (int q = 0; q < DD / 4; ++q)
            sXl[t * (DD / 4) + q] =
                make_float4(xl[4*q+0], xl[4*q+1], xl[4*q+2], xl[4*q+3]);
        sP[t] = var * (s1 + ((float)DD - 1.f - xs) * L);
        sH[t] = -0.5f * xs;
    }

    // ---- phase 2b: per-thread column transform (cols m0, m0+1) ----
    float a[DD], a2[DD], b[DD], b2[DD];
    float q0, h0, q1, h1;
    {
        // rows m0 and m0+1 of X2 are 128 contiguous bytes -> warp reads 16KB coalesced
        const float4* r = reinterpret_cast<const float4*>(X2 + (size_t)m0 * DD);
        float x2s0 = 0.f, s20 = 0.f, x2s1 = 0.f, s21 = 0.f;
#pragma unroll
        for (int q = 0; q < DD / 4; ++q) {
            float4 va = r[q];
            float4 vb = r[q + DD / 4];
            float t0, t1, t2, t3;
            t0 = va.x * inv_ls[4*q+0]; t1 = va.y * inv_ls[4*q+1];
            t2 = va.z * inv_ls[4*q+2]; t3 = va.w * inv_ls[4*q+3];
            a[4*q+0]=t0; a[4*q+1]=t1; a[4*q+2]=t2; a[4*q+3]=t3;
            a2[4*q+0]=t0*l2[4*q+0]; a2[4*q+1]=t1*l2[4*q+1];
            a2[4*q+2]=t2*l2[4*q+2]; a2[4*q+3]=t3*l2[4*q+3];
            x2s0 += t0*t0 + t1*t1 + t2*t2 + t3*t3;
            s20  += t0*t0*l2[4*q+0] + t1*t1*l2[4*q+1]
                  + t2*t2*l2[4*q+2] + t3*t3*l2[4*q+3];
            t0 = vb.x * inv_ls[4*q+0]; t1 = vb.y * inv_ls[4*q+1];
            t2 = vb.z * inv_ls[4*q+2]; t3 = vb.w * inv_ls[4*q+3];
            b[4*q+0]=t0; b[4*q+1]=t1; b[4*q+2]=t2; b[4*q+3]=t3;
            b2[4*q+0]=t0*l2[4*q+0]; b2[4*q+1]=t1*l2[4*q+1];
            b2[4*q+2]=t2*l2[4*q+2]; b2[4*q+3]=t3*l2[4*q+3];
            x2s1 += t0*t0 + t1*t1 + t2*t2 + t3*t3;
            s21  += t0*t0*l2[4*q+0] + t1*t1*l2[4*q+1]
                  + t2*t2*l2[4*q+2] + t3*t3*l2[4*q+3];
        }
        q0 = var * (s20 - x2s0 * L);  h0 = -0.5f * x2s0;
        q1 = var * (s21 - x2s1 * L);  h1 = -0.5f * x2s1;
    }
    __syncthreads();

    // ---- main loop: 16 rows x 2 cols per thread ----
#pragma unroll 4
    for (int n = 0; n < TILE_N; ++n) {
        float d0a = 0.f, dwa = 0.f, d0b = 0.f, dwb = 0.f;
#pragma unroll
        for (int q = 0; q < DD / 4; ++q) {
            float4 x4 = sXl[n * (DD / 4) + q];    // broadcast LDS.128
            d0a = fmaf(x4.x, a [4*q+0], d0a);  dwa = fmaf(x4.x, a2[4*q+0], dwa);
            d0a = fmaf(x4.y, a [4*q+1], d0a);  dwa = fmaf(x4.y, a2[4*q+1], dwa);
            d0a = fmaf(x4.z, a [4*q+2], d0a);  dwa = fmaf(x4.z, a2[4*q+2], dwa);
            d0a = fmaf(x4.w, a [4*q+3], d0a);  dwa = fmaf(x4.w, a2[4*q+3], dwa);
            d0b = fmaf(x4.x, b [4*q+0], d0b);  dwb = fmaf(x4.x, b2[4*q+0], dwb);
            d0b = fmaf(x4.y, b [4*q+1], d0b);  dwb = fmaf(x4.y, b2[4*q+1], dwb);
            d0b = fmaf(x4.z, b [4*q+2], d0b);  dwb = fmaf(x4.z, b2[4*q+2], dwb);
            d0b = fmaf(x4.w, b [4*q+3], d0b);  dwb = fmaf(x4.w, b2[4*q+3], dwb);
        }
        const float pn = sP[n], hn = sH[n];
        float e0 = __expf(hn + h0 + d0a);
        float e1 = __expf(hn + h1 + d0b);
        float r0 = fmaf(c1, d0a, pn + q0);  r0 = fmaf(-c2, dwa, r0);
        float r1 = fmaf(c1, d0b, pn + q1);  r1 = fmaf(-c2, dwb, r1);
        float2 o;
        o.x = e0 * r0;
        o.y = e1 * r1;
        *reinterpret_cast<float2*>(out + (size_t)(nb + n) * MM + m0) = o;
    }
}

// ---------------------------------------------------------------------------
extern "C" void kernel_launch(void* const* d_in, const int* in_sizes, int n_in,
                              void* d_out, int out_size)
{
    const float* X   = (const float*)d_in[0];   // (2048,16)
    const float* X2  = (const float*)d_in[1];   // (2048,16)
    const float* uls = (const float*)d_in[2];   // (16,)
    const float* uv  = (const float*)d_in[3];   // (1,)
    float* out = (float*)d_out;                 // (2048,2048)

    dim3 grid(MM / TILE_M, NN / TILE_N);        // (8, 128) = 1024 blocks
    fused_kernel<<<grid, BT>>>(X, X2, uls, uv, out);
}

// round 7
// speedup vs baseline: 1.3689x; 1.0835x over previous
#include <cuda_runtime.h>
#include <math.h>

constexpr int NN = 2048;
constexpr int MM = 2048;
constexpr int DD = 16;

constexpr int BT           = 128;       // threads per block
constexpr int ROWS_PER_BLK = 64;        // rows of X per block
constexpr int COLS_PER_BLK = 2 * BT;    // 256 cols of X2 per block (2/thread)

typedef unsigned long long u64;

// ---- packed fp32x2 ops (sm_103a; ptxas never emits FFMA2 from C++) ----
#define FMA2(d, a, b, c) asm("fma.rn.f32x2 %0, %1, %2, %3;" : "=l"(d) : "l"(a), "l"(b), "l"(c))
#define MUL2(d, a, b)    asm("mul.rn.f32x2 %0, %1, %2;"     : "=l"(d) : "l"(a), "l"(b))
#define ADD2(d, a, b)    asm("add.rn.f32x2 %0, %1, %2;"     : "=l"(d) : "l"(a), "l"(b))
#define PACK2(d, lo, hi) asm("mov.b64 %0, {%1, %2};"        : "=l"(d) : "f"(lo), "f"(hi))
#define UNPACK2(lo, hi, s) asm("mov.b64 {%0, %1}, %2;" : "=f"(lo), "=f"(hi) : "l"(s))
#define EX2(d, s)        asm("ex2.approx.f32 %0, %1;"       : "=f"(d) : "f"(s))

// (log2e, log2e) packed
#define LOG2E2 0x3FB8AA3B3FB8AA3BULL

// ---------------------------------------------------------------------------
// out[n,m] = exp(hXs[n]+hX2s[m]+Xl_n.X2l_m) * (P[n]+Q[m]+Xl_n.(X2l_m ∘ w))
//   w_d = c1 - c2*l2_d,  c1 = 2*var*L,  c2 = 2*var,  L = sum(l2)
// Block: 64 rows x 256 cols; thread owns cols (m0, m0+1) packed as f32x2.
// ---------------------------------------------------------------------------
__global__ __launch_bounds__(BT)
void fused_kernel(const float* __restrict__ X,
                  const float* __restrict__ X2,
                  const float* __restrict__ uls,
                  const float* __restrict__ uv,
                  float* __restrict__ out)
{
    __shared__ __align__(16) u64 sX2[ROWS_PER_BLK * DD];  // (x,x) dup pairs
    __shared__ u64  sH2[ROWS_PER_BLK];                    // (-xs/2, -xs/2)
    __shared__ u64  sP2[ROWS_PER_BLK];                    // (P[n], P[n])
    __shared__ float sInv[DD];
    __shared__ float sL2 [DD];
    __shared__ float sVar;

    const int t  = threadIdx.x;
    const int rb = blockIdx.y * ROWS_PER_BLK;
    const int m0 = blockIdx.x * COLS_PER_BLK + 2 * t;

    // ---- phase 1: softplus of hyperparams (17 scalars) ----
    if (t < DD) {
        float u = uls[t];
        float s = (u > 20.f) ? u : log1pf(expf(u));
        sInv[t] = 1.f / s;
        sL2[t]  = 1.f / (s * s);
    }
    if (t == DD) {
        float u = uv[0];
        sVar = (u > 20.f) ? u : log1pf(expf(u));
    }
    __syncthreads();

    float L = 0.f;
#pragma unroll
    for (int d = 0; d < DD; ++d) L += sL2[d];
    const float var = sVar;
    const float c1  = 2.f * var * L;
    const float c2  = 2.f * var;

    // ---- phase 2a: row prep, one row per thread (t < 64) ----
    if (t < ROWS_PER_BLK) {
        const float4* xr = reinterpret_cast<const float4*>(X + (size_t)(rb + t) * DD);
        float xl[DD];
        float xs = 0.f, s1 = 0.f;
#pragma unroll
        for (int q = 0; q < DD / 4; ++q) {
            float4 v = xr[q];
            float v0 = v.x * sInv[4*q+0], v1 = v.y * sInv[4*q+1];
            float v2 = v.z * sInv[4*q+2], v3 = v.w * sInv[4*q+3];
            xl[4*q+0] = v0; xl[4*q+1] = v1; xl[4*q+2] = v2; xl[4*q+3] = v3;
            xs += v0*v0 + v1*v1 + v2*v2 + v3*v3;
            s1 += v0*v0*sL2[4*q+0] + v1*v1*sL2[4*q+1]
                + v2*v2*sL2[4*q+2] + v3*v3*sL2[4*q+3];
        }
#pragma unroll
        for (int d = 0; d < DD; ++d) {
            u64 p; PACK2(p, xl[d], xl[d]);
            sX2[t * DD + d] = p;
        }
        float hn = -0.5f * xs;
        float pn = var * (s1 + ((float)DD - 1.f - xs) * L);
        u64 hp; PACK2(hp, hn, hn); sH2[t] = hp;
        u64 pp; PACK2(pp, pn, pn); sP2[t] = pp;
    }

    // ---- phase 2b: per-thread column transform, packed operands ----
    u64 A[DD], U[DD];
    u64 Qp, Hc;
    {
        const float4* r = reinterpret_cast<const float4*>(X2 + (size_t)m0 * DD);
        float x2s0 = 0.f, s20 = 0.f, x2s1 = 0.f, s21 = 0.f;
#pragma unroll
        for (int q = 0; q < DD / 4; ++q) {
            float4 va = r[q];
            float4 vb = r[q + DD / 4];
#pragma unroll
            for (int j = 0; j < 4; ++j) {
                int d = 4 * q + j;
                float inv = sInv[d], l2d = sL2[d];
                float aj = ((j == 0) ? va.x : (j == 1) ? va.y : (j == 2) ? va.z : va.w) * inv;
                float bj = ((j == 0) ? vb.x : (j == 1) ? vb.y : (j == 2) ? vb.z : vb.w) * inv;
                x2s0 += aj * aj;  s20 += aj * aj * l2d;
                x2s1 += bj * bj;  s21 += bj * bj * l2d;
                PACK2(A[d], aj, bj);
                float w = c1 - c2 * l2d;
                u64 ww; PACK2(ww, w, w);
                MUL2(U[d], A[d], ww);
            }
        }
        PACK2(Qp, var * (s20 - x2s0 * L), var * (s21 - x2s1 * L));
        PACK2(Hc, -0.5f * x2s0, -0.5f * x2s1);
    }
    __syncthreads();

    // ---- main loop: 64 rows, 2 cols per thread, all-packed f32x2 ----
    const u64 log2e2 = LOG2E2;
#pragma unroll 2
    for (int n = 0; n < ROWS_PER_BLK; ++n) {
        const ulonglong2* xv = reinterpret_cast<const ulonglong2*>(sX2 + n * DD);
        u64 p0 = 0, p1 = 0, w0 = 0, w1 = 0;   // split chains (8 FMA2 each)
#pragma unroll
        for (int q = 0; q < 8; ++q) {
            ulonglong2 xx = xv[q];             // LDS.128: two (x,x) pairs
            FMA2(p0, xx.x, A[2*q+0], p0);  FMA2(w0, xx.x, U[2*q+0], w0);
            FMA2(p1, xx.y, A[2*q+1], p1);  FMA2(w1, xx.y, U[2*q+1], w1);
        }
        u64 d0;  ADD2(d0, p0, p1);
        u64 du;  ADD2(du, w0, w1);

        u64 h2 = sH2[n];
        u64 arg; ADD2(arg, d0, Hc); ADD2(arg, arg, h2);
        MUL2(arg, arg, log2e2);
        float g0, g1; UNPACK2(g0, g1, arg);
        float e0, e1; EX2(e0, g0); EX2(e1, g1);

        u64 q2 = sP2[n];
        u64 poly; ADD2(poly, du, Qp); ADD2(poly, poly, q2);
        u64 E; PACK2(E, e0, e1);
        u64 o; MUL2(o, E, poly);

        *reinterpret_cast<u64*>(out + (size_t)(rb + n) * MM + m0) = o;
    }
}

// ---------------------------------------------------------------------------
extern "C" void kernel_launch(void* const* d_in, const int* in_sizes, int n_in,
                              void* d_out, int out_size)
{
    const float* X   = (const float*)d_in[0];   // (2048,16)
    const float* X2  = (const float*)d_in[1];   // (2048,16)
    const float* uls = (const float*)d_in[2];   // (16,)
    const float* uv  = (const float*)d_in[3];   // (1,)
    float* out = (float*)d_out;                 // (2048,2048)

    dim3 grid(MM / COLS_PER_BLK, NN / ROWS_PER_BLK);  // (8, 32) = 256 blocks
    fused_kernel<<<grid, BT>>>(X, X2, uls, uv, out);
}